// round 1
// baseline (speedup 1.0000x reference)
#include <cuda_runtime.h>
#include <math.h>

#define L 512
#define DS 384
#define DP 128
#define H_ 12
#define DH 32
#define PQ 4
#define PV 8
#define QPD 144   /* H*PQ*3 */
#define VPD 288   /* H*PV*3 */
#define COMBD 2304
#define IB 4

// ---------------- scratch (device globals; no runtime alloc) ----------------
__device__ float g_q[L*DS], g_k[L*DS], g_v[L*DS];
__device__ float g_qg[L*QPD], g_kg[L*QPD], g_vg[L*VPD];
__device__ float g_sqq[L*H_], g_sqk[L*H_];
__device__ float g_att[(size_t)H_*L*L];   // logits, then attn in-place
__device__ float g_comb[L*COMBD];

// ---------------- K1: LayerNorm + projections + rotations ----------------
__global__ void k_proj(const float* __restrict__ single_, const float* __restrict__ rot,
                       const float* __restrict__ trans,
                       const float* __restrict__ ln_w, const float* __restrict__ ln_b,
                       const float* __restrict__ Wq, const float* __restrict__ bq,
                       const float* __restrict__ Wk, const float* __restrict__ bk,
                       const float* __restrict__ Wv, const float* __restrict__ bv,
                       const float* __restrict__ Wqp, const float* __restrict__ bqp,
                       const float* __restrict__ Wkp, const float* __restrict__ bkp,
                       const float* __restrict__ Wvp, const float* __restrict__ bvp) {
    const int i = blockIdx.x;
    const int t = threadIdx.x;   // 384 threads

    __shared__ float sn[DS];
    __shared__ float red[512];
    __shared__ float qp_s[QPD], kp_s[QPD], vp_s[VPD];
    __shared__ float qg_s[QPD], kg_s[QPD];
    __shared__ float Rm[9], Tv[3];

    float x = single_[i*DS + t];
    red[t] = x;
    if (t < 128) red[384 + t] = 0.f;
    __syncthreads();
    for (int s = 256; s > 0; s >>= 1) { if (t < s) red[t] += red[t+s]; __syncthreads(); }
    float mu = red[0] * (1.f/384.f);
    __syncthreads();
    float xc = x - mu;
    red[t] = xc*xc;
    if (t < 128) red[384 + t] = 0.f;
    __syncthreads();
    for (int s = 256; s > 0; s >>= 1) { if (t < s) red[t] += red[t+s]; __syncthreads(); }
    float var = red[0] * (1.f/384.f);
    float sni = xc * rsqrtf(var + 1e-5f) * ln_w[t] + ln_b[t];
    sn[t] = sni;
    if (t < 9) Rm[t] = rot[i*9 + t];
    if (t < 3) Tv[t] = trans[i*3 + t];
    __syncthreads();

    // q, k, v (out dim = t)
    {
        float aq = bq[t], ak = bk[t], av = bv[t];
        #pragma unroll 4
        for (int d = 0; d < DS; d++) {
            float s = sn[d];
            aq += s * Wq[d*DS + t];
            ak += s * Wk[d*DS + t];
            av += s * Wv[d*DS + t];
        }
        g_q[i*DS + t] = aq; g_k[i*DS + t] = ak; g_v[i*DS + t] = av;
    }
    if (t < QPD) {
        float a = bqp[t], b2 = bkp[t];
        #pragma unroll 4
        for (int d = 0; d < DS; d++) {
            float s = sn[d];
            a  += s * Wqp[d*QPD + t];
            b2 += s * Wkp[d*QPD + t];
        }
        qp_s[t] = a; kp_s[t] = b2;
    }
    if (t < VPD) {
        float a = bvp[t];
        #pragma unroll 4
        for (int d = 0; d < DS; d++) a += sn[d] * Wvp[d*VPD + t];
        vp_s[t] = a;
    }
    __syncthreads();

    // rotate points: g = R * p + T
    if (t < QPD) {
        int i3 = t % 3, base = t - i3;
        float qg = Rm[i3*3+0]*qp_s[base] + Rm[i3*3+1]*qp_s[base+1] + Rm[i3*3+2]*qp_s[base+2] + Tv[i3];
        float kg = Rm[i3*3+0]*kp_s[base] + Rm[i3*3+1]*kp_s[base+1] + Rm[i3*3+2]*kp_s[base+2] + Tv[i3];
        qg_s[t] = qg; kg_s[t] = kg;
        g_qg[i*QPD + t] = qg; g_kg[i*QPD + t] = kg;
    }
    if (t < VPD) {
        int i3 = t % 3, base = t - i3;
        float vg = Rm[i3*3+0]*vp_s[base] + Rm[i3*3+1]*vp_s[base+1] + Rm[i3*3+2]*vp_s[base+2] + Tv[i3];
        g_vg[i*VPD + t] = vg;
    }
    __syncthreads();
    if (t < H_) {
        float sq = 0.f, sk = 0.f;
        #pragma unroll
        for (int u = 0; u < 12; u++) {
            float a = qg_s[t*12 + u]; sq += a*a;
            float b = kg_s[t*12 + u]; sk += b*b;
        }
        g_sqq[i*H_ + t] = sq; g_sqk[i*H_ + t] = sk;
    }
}

// ---------------- K2: seq + geo logits ----------------
__global__ void k_logits(const float* __restrict__ wc, const float* __restrict__ wl,
                         const float* __restrict__ gamma) {
    const int h = blockIdx.z;
    const int i0 = blockIdx.y*32, j0 = blockIdx.x*32;
    const int tx = threadIdx.x, ty = threadIdx.y;

    __shared__ float qs[32][33], ks[32][33];
    __shared__ float qgs[32][12], kgs[32][12];
    __shared__ float sqi[32], sqj[32];

    qs[ty][tx] = g_q[(i0+ty)*DS + h*DH + tx];
    ks[ty][tx] = g_k[(j0+ty)*DS + h*DH + tx];
    if (tx < 12) {
        qgs[ty][tx] = g_qg[(i0+ty)*QPD + h*12 + tx];
        kgs[ty][tx] = g_kg[(j0+ty)*QPD + h*12 + tx];
    }
    if (tx == 0) {
        sqi[ty] = g_sqq[(i0+ty)*H_ + h];
        sqj[ty] = g_sqk[(j0+ty)*H_ + h];
    }
    __syncthreads();

    const float cseq = wc[0] * rsqrtf((float)DH);
    const float cg   = gamma[h] * wl[0];

    float acc = 0.f;
    #pragma unroll
    for (int d = 0; d < 32; d++) acc += qs[ty][d] * ks[tx][d];
    acc *= cseq;
    float accg = 0.f;
    #pragma unroll
    for (int d = 0; d < 12; d++) accg += qgs[ty][d] * kgs[tx][d];
    acc += cg*accg - 0.5f*cg*(sqi[ty] + sqj[tx]);

    g_att[((size_t)h*L + (i0+ty))*L + (j0+tx)] = acc;
}

// ---------------- K3: pair bias + mask + softmax ----------------
__global__ void k_softmax(const float* __restrict__ pair, const float* __restrict__ Wpb,
                          const float* __restrict__ bpb, const float* __restrict__ mask) {
    const int i = blockIdx.x;
    const int t = threadIdx.x;   // 256 threads

    __shared__ float lg[H_*L];        // 24 KB
    __shared__ float wpb_s[DP*H_];    // 6 KB
    __shared__ float bpb_s[H_];
    __shared__ float red[256];

    for (int idx = t; idx < DP*H_; idx += 256) wpb_s[idx] = Wpb[idx];
    if (t < H_) bpb_s[t] = bpb[t];
    for (int idx = t; idx < H_*L; idx += 256) {
        int h = idx >> 9, j = idx & 511;
        lg[idx] = g_att[((size_t)h*L + i)*L + j];
    }
    __syncthreads();

    const float mi = mask[i];
    for (int j = t; j < L; j += 256) {
        const float4* pr = (const float4*)(pair + ((size_t)i*L + j)*DP);
        float acc[H_];
        #pragma unroll
        for (int h = 0; h < H_; h++) acc[h] = bpb_s[h];
        #pragma unroll 8
        for (int c = 0; c < 32; c++) {
            float4 p = pr[c];
            const float* w0 = &wpb_s[(c*4)*H_];
            #pragma unroll
            for (int h = 0; h < H_; h++)
                acc[h] += p.x*w0[h] + p.y*w0[12+h] + p.z*w0[24+h] + p.w*w0[36+h];
        }
        bool valid = (mi * mask[j]) > 0.f;
        #pragma unroll
        for (int h = 0; h < H_; h++) {
            float v2 = lg[h*L + j] + acc[h];
            lg[h*L + j] = valid ? v2 : -1e9f;
        }
    }
    __syncthreads();

    for (int h = 0; h < H_; h++) {
        float* row = &lg[h*L];
        float m = fmaxf(row[t], row[t+256]);
        red[t] = m; __syncthreads();
        for (int s = 128; s > 0; s >>= 1) { if (t < s) red[t] = fmaxf(red[t], red[t+s]); __syncthreads(); }
        m = red[0]; __syncthreads();
        float e0 = __expf(row[t]-m), e1 = __expf(row[t+256]-m);
        red[t] = e0 + e1; __syncthreads();
        for (int s = 128; s > 0; s >>= 1) { if (t < s) red[t] += red[t+s]; __syncthreads(); }
        float inv = 1.f / red[0]; __syncthreads();
        g_att[((size_t)h*L + i)*L + t]       = e0 * inv;
        g_att[((size_t)h*L + i)*L + t + 256] = e1 * inv;
    }
}

// ---------------- K4: attn-weighted outputs (seq, pts, pair) ----------------
__global__ void k_out(const float* __restrict__ pair, const float* __restrict__ rot,
                      const float* __restrict__ trans) {
    extern __shared__ float sm[];
    float* arow  = sm;                   // IB*6144
    float* ptile = sm + IB*6144;         // IB*32*128 = 16384
    float* pts_s = ptile + 16384;        // IB*288

    const int i0 = blockIdx.x * IB;
    const int t  = threadIdx.x;          // 384 threads

    for (int idx = t; idx < IB*H_*L; idx += 384) {
        int ii = idx / 6144; int rem = idx - ii*6144;
        int h = rem >> 9, j = rem & 511;
        arow[idx] = g_att[((size_t)h*L + (i0+ii))*L + j];
    }
    __syncthreads();

    // phase 1: seq_out (v) and raw pts_out (vg)
    float acc0[IB] = {0,0,0,0};
    float acc1[IB] = {0,0,0,0};
    const int h0 = t >> 5;
    const int h1 = (t < VPD) ? (t / 24) : 0;
    for (int j = 0; j < L; j++) {
        float vv = g_v[j*DS + t];
        #pragma unroll
        for (int ii = 0; ii < IB; ii++) acc0[ii] += arow[ii*6144 + h0*512 + j] * vv;
        if (t < VPD) {
            float vgv = g_vg[j*VPD + t];
            #pragma unroll
            for (int ii = 0; ii < IB; ii++) acc1[ii] += arow[ii*6144 + h1*512 + j] * vgv;
        }
    }
    #pragma unroll
    for (int ii = 0; ii < IB; ii++) g_comb[(i0+ii)*COMBD + t] = acc0[ii];
    if (t < VPD) {
        #pragma unroll
        for (int ii = 0; ii < IB; ii++) pts_s[ii*VPD + t] = acc1[ii];
    }
    __syncthreads();

    // phase 2: pts -> local frame + norm   (IB*96 == 384 == blockDim)
    {
        int ii = t / 96, u = t % 96;
        int gi = i0 + ii;
        float R0=rot[gi*9+0],R1=rot[gi*9+1],R2=rot[gi*9+2];
        float R3=rot[gi*9+3],R4=rot[gi*9+4],R5=rot[gi*9+5];
        float R6=rot[gi*9+6],R7=rot[gi*9+7],R8=rot[gi*9+8];
        float T0=trans[gi*3+0],T1=trans[gi*3+1],T2=trans[gi*3+2];
        float px = pts_s[ii*VPD + u*3+0] - T0;
        float py = pts_s[ii*VPD + u*3+1] - T1;
        float pz = pts_s[ii*VPD + u*3+2] - T2;
        float lx = R0*px + R3*py + R6*pz;   // R^T * p
        float ly = R1*px + R4*py + R7*pz;
        float lz = R2*px + R5*py + R8*pz;
        float nrm = sqrtf(lx*lx + ly*ly + lz*lz);
        float* dst = &g_comb[gi*COMBD + 384 + u*4];
        dst[0]=nrm; dst[1]=lx; dst[2]=ly; dst[3]=lz;
    }

    // phase 3: pair_out with smem-staged pair tiles
    const int c4 = (t & 31) * 4;
    const int hh = t >> 5;
    float accp[IB][4] = {};
    for (int j0 = 0; j0 < L; j0 += 32) {
        __syncthreads();
        for (int idx = t; idx < IB*32*DP; idx += 384) {
            int ii = idx >> 12; int rem = idx & 4095;
            int jj = rem >> 7;  int c = rem & 127;
            ptile[idx] = pair[(((size_t)(i0+ii))*L + (j0+jj))*DP + c];
        }
        __syncthreads();
        #pragma unroll 4
        for (int jj = 0; jj < 32; jj++) {
            int j = j0 + jj;
            #pragma unroll
            for (int ii = 0; ii < IB; ii++) {
                float a = arow[ii*6144 + hh*512 + j];
                const float4 pv = *(const float4*)&ptile[ii*4096 + jj*128 + c4];
                accp[ii][0] += a*pv.x; accp[ii][1] += a*pv.y;
                accp[ii][2] += a*pv.z; accp[ii][3] += a*pv.w;
            }
        }
    }
    #pragma unroll
    for (int ii = 0; ii < IB; ii++) {
        float* dst = &g_comb[(i0+ii)*COMBD + 768 + hh*128 + c4];
        dst[0]=accp[ii][0]; dst[1]=accp[ii][1]; dst[2]=accp[ii][2]; dst[3]=accp[ii][3];
    }
}

// ---------------- K5: combined @ Wo + bo ----------------
__global__ void k_final(const float* __restrict__ Wo, const float* __restrict__ bo,
                        float* __restrict__ out) {
    const int n0 = blockIdx.x * 32;
    const int m0 = blockIdx.y * 32;
    const int tx = threadIdx.x & 15;
    const int ty = threadIdx.x >> 4;

    __shared__ float As[32][33], Bs[32][33];
    float acc[2][2] = {};

    for (int k0 = 0; k0 < COMBD; k0 += 32) {
        for (int l = threadIdx.x; l < 1024; l += 256) {
            int m = l >> 5, k = l & 31;
            As[m][k] = g_comb[(m0+m)*COMBD + k0 + k];
        }
        for (int l = threadIdx.x; l < 1024; l += 256) {
            int k = l >> 5, n = l & 31;
            Bs[k][n] = Wo[(k0+k)*DS + n0 + n];
        }
        __syncthreads();
        #pragma unroll
        for (int k = 0; k < 32; k++) {
            float a0 = As[ty*2+0][k], a1 = As[ty*2+1][k];
            float b0 = Bs[k][tx*2+0], b1 = Bs[k][tx*2+1];
            acc[0][0] += a0*b0; acc[0][1] += a0*b1;
            acc[1][0] += a1*b0; acc[1][1] += a1*b1;
        }
        __syncthreads();
    }
    float bb0 = bo[n0 + tx*2 + 0], bb1 = bo[n0 + tx*2 + 1];
    out[(m0+ty*2+0)*DS + n0 + tx*2 + 0] = acc[0][0] + bb0;
    out[(m0+ty*2+0)*DS + n0 + tx*2 + 1] = acc[0][1] + bb1;
    out[(m0+ty*2+1)*DS + n0 + tx*2 + 0] = acc[1][0] + bb0;
    out[(m0+ty*2+1)*DS + n0 + tx*2 + 1] = acc[1][1] + bb1;
}

// ---------------- launch ----------------
extern "C" void kernel_launch(void* const* d_in, const int* in_sizes, int n_in,
                              void* d_out, int out_size) {
    const float* single_ = (const float*)d_in[0];
    const float* pair    = (const float*)d_in[1];
    const float* rot     = (const float*)d_in[2];
    const float* trans   = (const float*)d_in[3];
    const float* mask    = (const float*)d_in[4];
    const float* ln_w    = (const float*)d_in[5];
    const float* ln_b    = (const float*)d_in[6];
    const float* Wq      = (const float*)d_in[7];
    const float* bq      = (const float*)d_in[8];
    const float* Wk      = (const float*)d_in[9];
    const float* bk      = (const float*)d_in[10];
    const float* Wv      = (const float*)d_in[11];
    const float* bv      = (const float*)d_in[12];
    const float* Wqp     = (const float*)d_in[13];
    const float* bqp     = (const float*)d_in[14];
    const float* Wkp     = (const float*)d_in[15];
    const float* bkp     = (const float*)d_in[16];
    const float* Wvp     = (const float*)d_in[17];
    const float* bvp     = (const float*)d_in[18];
    const float* Wpb     = (const float*)d_in[19];
    const float* bpb     = (const float*)d_in[20];
    const float* Wo      = (const float*)d_in[21];
    const float* bo      = (const float*)d_in[22];
    const float* w_c     = (const float*)d_in[23];
    const float* w_l     = (const float*)d_in[24];
    const float* gamma_h = (const float*)d_in[25];

    k_proj<<<L, 384>>>(single_, rot, trans, ln_w, ln_b,
                       Wq, bq, Wk, bk, Wv, bv, Wqp, bqp, Wkp, bkp, Wvp, bvp);

    k_logits<<<dim3(16,16,12), dim3(32,32)>>>(w_c, w_l, gamma_h);

    k_softmax<<<L, 256>>>(pair, Wpb, bpb, mask);

    const int dyn = (IB*6144 + 16384 + IB*VPD) * (int)sizeof(float);  // 168448
    cudaFuncSetAttribute(k_out, cudaFuncAttributeMaxDynamicSharedMemorySize, dyn);
    k_out<<<L/IB, 384, dyn>>>(pair, rot, trans);

    k_final<<<dim3(DS/32, L/32), 256>>>(Wo, bo, (float*)d_out);
}

// round 2
// speedup vs baseline: 1.9496x; 1.9496x over previous
#include <cuda_runtime.h>
#include <math.h>

#define L 512
#define DS 384
#define DP 128
#define H_ 12
#define DH 32
#define PQ 4
#define PV 8
#define QPD 144
#define VPD 288
#define PROJD 1728
#define AVD 768
#define COMBD 2304

// ---------------- scratch ----------------
__device__ float g_sn[L*DS];
__device__ float g_proj[L*PROJD];          // q|k|v|qp|kp|vp
__device__ float g_qg[L*QPD], g_kg[L*QPD];
__device__ float g_sqq[L*H_], g_sqk[L*H_];
__device__ float g_avin[L*AVD];            // v(384) | vg padded 12*32
__device__ float g_att[(size_t)H_*L*L];
__device__ float g_ptsraw[L*H_*32];
__device__ float g_comb[L*COMBD];

// ---------------- K1: LayerNorm ----------------
__global__ void k_ln(const float* __restrict__ single_, const float* __restrict__ ln_w,
                     const float* __restrict__ ln_b) {
    const int i = blockIdx.x, t = threadIdx.x;  // 384
    __shared__ float red[512];
    float x = single_[i*DS + t];
    red[t] = x;
    if (t < 128) red[384+t] = 0.f;
    __syncthreads();
    for (int s = 256; s > 0; s >>= 1) { if (t < s) red[t] += red[t+s]; __syncthreads(); }
    float mu = red[0] * (1.f/384.f);
    __syncthreads();
    float xc = x - mu;
    red[t] = xc*xc;
    if (t < 128) red[384+t] = 0.f;
    __syncthreads();
    for (int s = 256; s > 0; s >>= 1) { if (t < s) red[t] += red[t+s]; __syncthreads(); }
    float var = red[0] * (1.f/384.f);
    g_sn[i*DS + t] = xc * rsqrtf(var + 1e-5f) * ln_w[t] + ln_b[t];
}

// ---------------- K2: projection GEMM (sn @ [Wq|Wk|Wv|Wqp|Wkp|Wvp]) ----------------
__device__ __forceinline__ void seg_of(int c, const float* Wq, const float* Wk, const float* Wv,
                                       const float* Wqp, const float* Wkp, const float* Wvp,
                                       const float** W, int* w, int* lc) {
    if (c < 384)       { *W = Wq;  *w = 384; *lc = c; }
    else if (c < 768)  { *W = Wk;  *w = 384; *lc = c-384; }
    else if (c < 1152) { *W = Wv;  *w = 384; *lc = c-768; }
    else if (c < 1296) { *W = Wqp; *w = 144; *lc = c-1152; }
    else if (c < 1440) { *W = Wkp; *w = 144; *lc = c-1296; }
    else               { *W = Wvp; *w = 288; *lc = c-1440; }
}
__device__ __forceinline__ float bias_of(int c, const float* bq, const float* bk, const float* bv,
                                         const float* bqp, const float* bkp, const float* bvp) {
    if (c < 384) return bq[c];
    if (c < 768) return bk[c-384];
    if (c < 1152) return bv[c-768];
    if (c < 1296) return bqp[c-1152];
    if (c < 1440) return bkp[c-1296];
    return bvp[c-1440];
}

__global__ void k_projgemm(const float* __restrict__ Wq, const float* __restrict__ bq,
                           const float* __restrict__ Wk, const float* __restrict__ bk,
                           const float* __restrict__ Wv, const float* __restrict__ bv,
                           const float* __restrict__ Wqp, const float* __restrict__ bqp,
                           const float* __restrict__ Wkp, const float* __restrict__ bkp,
                           const float* __restrict__ Wvp, const float* __restrict__ bvp) {
    const int n0 = blockIdx.x*32, m0 = blockIdx.y*32;
    const int tx = threadIdx.x & 15, ty = threadIdx.x >> 4;
    __shared__ float As[32][33], Bs[32][33];
    float acc[2][2] = {};

    for (int k0 = 0; k0 < DS; k0 += 32) {
        for (int l = threadIdx.x; l < 1024; l += 256) {
            int m = l >> 5, k = l & 31;
            As[m][k] = g_sn[(m0+m)*DS + k0 + k];
        }
        for (int l = threadIdx.x; l < 1024; l += 256) {
            int k = l >> 5, n = l & 31;
            const float* W; int w, lc;
            seg_of(n0+n, Wq, Wk, Wv, Wqp, Wkp, Wvp, &W, &w, &lc);
            Bs[k][n] = W[(k0+k)*w + lc];
        }
        __syncthreads();
        #pragma unroll
        for (int k = 0; k < 32; k++) {
            float a0 = As[ty*2+0][k], a1 = As[ty*2+1][k];
            float b0 = Bs[k][tx*2+0], b1 = Bs[k][tx*2+1];
            acc[0][0] += a0*b0; acc[0][1] += a0*b1;
            acc[1][0] += a1*b0; acc[1][1] += a1*b1;
        }
        __syncthreads();
    }
    float bb0 = bias_of(n0+tx*2+0, bq, bk, bv, bqp, bkp, bvp);
    float bb1 = bias_of(n0+tx*2+1, bq, bk, bv, bqp, bkp, bvp);
    g_proj[(m0+ty*2+0)*PROJD + n0+tx*2+0] = acc[0][0] + bb0;
    g_proj[(m0+ty*2+0)*PROJD + n0+tx*2+1] = acc[0][1] + bb1;
    g_proj[(m0+ty*2+1)*PROJD + n0+tx*2+0] = acc[1][0] + bb0;
    g_proj[(m0+ty*2+1)*PROJD + n0+tx*2+1] = acc[1][1] + bb1;
}

// ---------------- K3: rotations + avin assembly + point sq-norms ----------------
__global__ void k_rot(const float* __restrict__ rot, const float* __restrict__ trans) {
    const int i = blockIdx.x, t = threadIdx.x;  // 384
    __shared__ float Rm[9], Tv[3];
    __shared__ float qg_s[QPD], kg_s[QPD];
    if (t < 9) Rm[t] = rot[i*9 + t];
    if (t < 3) Tv[t] = trans[i*3 + t];
    __syncthreads();
    const float* pr = &g_proj[i*PROJD];
    if (t < QPD) {
        int i3 = t % 3, base = t - i3;
        float q0 = pr[1152+base], q1 = pr[1152+base+1], q2 = pr[1152+base+2];
        float p0 = pr[1296+base], p1 = pr[1296+base+1], p2 = pr[1296+base+2];
        float qg = Rm[i3*3+0]*q0 + Rm[i3*3+1]*q1 + Rm[i3*3+2]*q2 + Tv[i3];
        float kg = Rm[i3*3+0]*p0 + Rm[i3*3+1]*p1 + Rm[i3*3+2]*p2 + Tv[i3];
        qg_s[t] = qg; kg_s[t] = kg;
        g_qg[i*QPD + t] = qg; g_kg[i*QPD + t] = kg;
    }
    if (t < VPD) {
        int i3 = t % 3, base = t - i3;
        float v0 = pr[1440+base], v1 = pr[1440+base+1], v2 = pr[1440+base+2];
        float vg = Rm[i3*3+0]*v0 + Rm[i3*3+1]*v1 + Rm[i3*3+2]*v2 + Tv[i3];
        int h = t / 24, r = t % 24;
        g_avin[i*AVD + 384 + h*32 + r] = vg;
    }
    if (t < 96) { int h = t/8, r = t%8; g_avin[i*AVD + 384 + h*32 + 24 + r] = 0.f; }
    g_avin[i*AVD + t] = pr[768 + t];
    __syncthreads();
    if (t < H_) {
        float sq = 0.f, sk = 0.f;
        #pragma unroll
        for (int u = 0; u < 12; u++) {
            float a = qg_s[t*12+u]; sq += a*a;
            float b = kg_s[t*12+u]; sk += b*b;
        }
        g_sqq[i*H_ + t] = sq; g_sqk[i*H_ + t] = sk;
    }
}

// ---------------- K4: seq + geo logits ----------------
__global__ void k_logits(const float* __restrict__ wc, const float* __restrict__ wl,
                         const float* __restrict__ gamma) {
    const int h = blockIdx.z;
    const int i0 = blockIdx.y*32, j0 = blockIdx.x*32;
    const int tx = threadIdx.x, ty = threadIdx.y;

    __shared__ float qs[32][33], ks[32][33];
    __shared__ float qgs[32][12], kgs[32][12];
    __shared__ float sqi[32], sqj[32];

    qs[ty][tx] = g_proj[(i0+ty)*PROJD + h*DH + tx];
    ks[ty][tx] = g_proj[(j0+ty)*PROJD + 384 + h*DH + tx];
    if (tx < 12) {
        qgs[ty][tx] = g_qg[(i0+ty)*QPD + h*12 + tx];
        kgs[ty][tx] = g_kg[(j0+ty)*QPD + h*12 + tx];
    }
    if (tx == 0) { sqi[ty] = g_sqq[(i0+ty)*H_ + h]; sqj[ty] = g_sqk[(j0+ty)*H_ + h]; }
    __syncthreads();

    const float cseq = wc[0] * rsqrtf((float)DH);
    const float cg   = gamma[h] * wl[0];

    float acc = 0.f;
    #pragma unroll
    for (int d = 0; d < 32; d++) acc += qs[ty][d] * ks[tx][d];
    acc *= cseq;
    float accg = 0.f;
    #pragma unroll
    for (int d = 0; d < 12; d++) accg += qgs[ty][d] * kgs[tx][d];
    acc += cg*accg - 0.5f*cg*(sqi[ty] + sqj[tx]);

    g_att[((size_t)h*L + (i0+ty))*L + (j0+tx)] = acc;
}

// ---------------- K5: fused pair-bias + softmax + pair_out (per row i) ----------------
__global__ void k_fused(const float* __restrict__ pair, const float* __restrict__ Wpb,
                        const float* __restrict__ bpb, const float* __restrict__ mask) {
    extern __shared__ float sm[];
    float* lg    = sm;          // 6144
    float* wpb_s = sm + 6144;   // 1536 ([c][h])
    float* part  = sm + 7680;   // 6144
    __shared__ float bpb_s[H_];

    const int i = blockIdx.x;
    const int t = threadIdx.x;  // 512

    for (int idx = t; idx < DP*H_; idx += 512) wpb_s[idx] = Wpb[idx];
    if (t < H_) bpb_s[t] = bpb[t];
    for (int idx = t; idx < H_*L; idx += 512) {
        int h = idx >> 9, j = idx & 511;
        lg[idx] = g_att[((size_t)h*L + i)*L + j];
    }
    __syncthreads();

    // ---- bias: one j per thread ----
    {
        const int j = t;
        const float4* pr = (const float4*)(pair + ((size_t)i*L + j)*DP);
        float acc[H_];
        #pragma unroll
        for (int h = 0; h < H_; h++) acc[h] = bpb_s[h];
        #pragma unroll 4
        for (int c4 = 0; c4 < 32; c4++) {
            float4 p = pr[c4];
            const float* w0 = &wpb_s[c4*48];
            #pragma unroll
            for (int h = 0; h < H_; h++)
                acc[h] += p.x*w0[h] + p.y*w0[12+h] + p.z*w0[24+h] + p.w*w0[36+h];
        }
        float mv = mask[i] * mask[j];
        #pragma unroll
        for (int h = 0; h < H_; h++) {
            float v2 = lg[h*L + j] + acc[h];
            lg[h*L + j] = (mv > 0.f) ? v2 : -1e9f;
        }
    }
    __syncthreads();

    // ---- softmax: warp per head ----
    {
        const int w = t >> 5, lane = t & 31;
        if (w < H_) {
            float* row = &lg[w*L];
            float m = -1e30f;
            for (int j = lane; j < L; j += 32) m = fmaxf(m, row[j]);
            #pragma unroll
            for (int o = 16; o; o >>= 1) m = fmaxf(m, __shfl_xor_sync(0xffffffffu, m, o));
            float s = 0.f;
            for (int j = lane; j < L; j += 32) { float e = __expf(row[j]-m); row[j] = e; s += e; }
            #pragma unroll
            for (int o = 16; o; o >>= 1) s += __shfl_xor_sync(0xffffffffu, s, o);
            float inv = 1.f / s;
            for (int j = lane; j < L; j += 32) {
                float a = row[j] * inv;
                row[j] = a;
                g_att[((size_t)w*L + i)*L + j] = a;
            }
        }
    }
    __syncthreads();

    // ---- pair_out: (j-group, channel) org, 12-head register accumulators ----
    {
        const int g = t >> 7, c = t & 127;
        float acc[H_] = {};
        const float* prow = pair + ((size_t)i*L + g*128)*DP + c;
        const float* lgj = &lg[g*128];
        #pragma unroll 2
        for (int jj = 0; jj < 128; jj++) {
            float p = prow[(size_t)jj*DP];
            #pragma unroll
            for (int h = 0; h < H_; h++) acc[h] += lgj[h*L + jj] * p;
        }
        #pragma unroll
        for (int h = 0; h < H_; h++) part[g*1536 + h*DP + c] = acc[h];
    }
    __syncthreads();
    for (int idx = t; idx < 1536; idx += 512)
        g_comb[(size_t)i*COMBD + 768 + idx] =
            part[idx] + part[1536+idx] + part[3072+idx] + part[4608+idx];
}

// ---------------- K6: attn @ [v | vg] tiled GEMM ----------------
__global__ void k_av() {
    const int bx = blockIdx.x;            // 0..23
    const int ch0 = bx*32;
    const int h = (bx < 12) ? bx : bx - 12;
    const int m0 = blockIdx.y*32;
    const int tx = threadIdx.x & 15, ty = threadIdx.x >> 4;

    __shared__ float As[32][33], Bs[32][33];
    float acc[2][2] = {};

    for (int j0 = 0; j0 < L; j0 += 32) {
        for (int l = threadIdx.x; l < 1024; l += 256) {
            int m = l >> 5, jj = l & 31;
            As[m][jj] = g_att[((size_t)h*L + m0+m)*L + j0+jj];
        }
        for (int l = threadIdx.x; l < 1024; l += 256) {
            int jj = l >> 5, cc = l & 31;
            Bs[jj][cc] = g_avin[(j0+jj)*AVD + ch0+cc];
        }
        __syncthreads();
        #pragma unroll
        for (int k = 0; k < 32; k++) {
            float a0 = As[ty*2+0][k], a1 = As[ty*2+1][k];
            float b0 = Bs[k][tx*2+0], b1 = Bs[k][tx*2+1];
            acc[0][0] += a0*b0; acc[0][1] += a0*b1;
            acc[1][0] += a1*b0; acc[1][1] += a1*b1;
        }
        __syncthreads();
    }
    if (bx < 12) {
        #pragma unroll
        for (int a = 0; a < 2; a++)
            #pragma unroll
            for (int b = 0; b < 2; b++)
                g_comb[(size_t)(m0+ty*2+a)*COMBD + ch0 + tx*2+b] = acc[a][b];
    } else {
        #pragma unroll
        for (int a = 0; a < 2; a++)
            #pragma unroll
            for (int b = 0; b < 2; b++)
                g_ptsraw[(m0+ty*2+a)*384 + (ch0-384) + tx*2+b] = acc[a][b];
    }
}

// ---------------- K7: point frame transform + norm ----------------
__global__ void k_pts(const float* __restrict__ rot, const float* __restrict__ trans) {
    int idx = blockIdx.x*256 + threadIdx.x;
    if (idx >= L*96) return;
    int i = idx / 96, u = idx % 96;
    int h = u >> 3, p = u & 7;
    const float* src = &g_ptsraw[i*384 + h*32 + p*3];
    float T0 = trans[i*3+0], T1 = trans[i*3+1], T2 = trans[i*3+2];
    float px = src[0]-T0, py = src[1]-T1, pz = src[2]-T2;
    const float* R = &rot[i*9];
    float lx = R[0]*px + R[3]*py + R[6]*pz;
    float ly = R[1]*px + R[4]*py + R[7]*pz;
    float lz = R[2]*px + R[5]*py + R[8]*pz;
    float nrm = sqrtf(lx*lx + ly*ly + lz*lz);
    float* dst = &g_comb[(size_t)i*COMBD + 384 + u*4];
    dst[0] = nrm; dst[1] = lx; dst[2] = ly; dst[3] = lz;
}

// ---------------- K8: combined @ Wo + bo ----------------
__global__ void k_final(const float* __restrict__ Wo, const float* __restrict__ bo,
                        float* __restrict__ out) {
    const int n0 = blockIdx.x*32, m0 = blockIdx.y*32;
    const int tx = threadIdx.x & 15, ty = threadIdx.x >> 4;
    __shared__ float As[32][33], Bs[32][33];
    float acc[2][2] = {};

    for (int k0 = 0; k0 < COMBD; k0 += 32) {
        for (int l = threadIdx.x; l < 1024; l += 256) {
            int m = l >> 5, k = l & 31;
            As[m][k] = g_comb[(size_t)(m0+m)*COMBD + k0 + k];
        }
        for (int l = threadIdx.x; l < 1024; l += 256) {
            int k = l >> 5, n = l & 31;
            Bs[k][n] = Wo[(size_t)(k0+k)*DS + n0 + n];
        }
        __syncthreads();
        #pragma unroll
        for (int k = 0; k < 32; k++) {
            float a0 = As[ty*2+0][k], a1 = As[ty*2+1][k];
            float b0 = Bs[k][tx*2+0], b1 = Bs[k][tx*2+1];
            acc[0][0] += a0*b0; acc[0][1] += a0*b1;
            acc[1][0] += a1*b0; acc[1][1] += a1*b1;
        }
        __syncthreads();
    }
    float bb0 = bo[n0+tx*2+0], bb1 = bo[n0+tx*2+1];
    out[(m0+ty*2+0)*DS + n0+tx*2+0] = acc[0][0] + bb0;
    out[(m0+ty*2+0)*DS + n0+tx*2+1] = acc[0][1] + bb1;
    out[(m0+ty*2+1)*DS + n0+tx*2+0] = acc[1][0] + bb0;
    out[(m0+ty*2+1)*DS + n0+tx*2+1] = acc[1][1] + bb1;
}

// ---------------- launch ----------------
extern "C" void kernel_launch(void* const* d_in, const int* in_sizes, int n_in,
                              void* d_out, int out_size) {
    const float* single_ = (const float*)d_in[0];
    const float* pair    = (const float*)d_in[1];
    const float* rot     = (const float*)d_in[2];
    const float* trans   = (const float*)d_in[3];
    const float* mask    = (const float*)d_in[4];
    const float* ln_w    = (const float*)d_in[5];
    const float* ln_b    = (const float*)d_in[6];
    const float* Wq      = (const float*)d_in[7];
    const float* bq      = (const float*)d_in[8];
    const float* Wk      = (const float*)d_in[9];
    const float* bk      = (const float*)d_in[10];
    const float* Wv      = (const float*)d_in[11];
    const float* bv      = (const float*)d_in[12];
    const float* Wqp     = (const float*)d_in[13];
    const float* bqp     = (const float*)d_in[14];
    const float* Wkp     = (const float*)d_in[15];
    const float* bkp     = (const float*)d_in[16];
    const float* Wvp     = (const float*)d_in[17];
    const float* bvp     = (const float*)d_in[18];
    const float* Wpb     = (const float*)d_in[19];
    const float* bpb     = (const float*)d_in[20];
    const float* Wo      = (const float*)d_in[21];
    const float* bo      = (const float*)d_in[22];
    const float* w_c     = (const float*)d_in[23];
    const float* w_l     = (const float*)d_in[24];
    const float* gamma_h = (const float*)d_in[25];

    k_ln<<<L, 384>>>(single_, ln_w, ln_b);
    k_projgemm<<<dim3(PROJD/32, L/32), 256>>>(Wq, bq, Wk, bk, Wv, bv,
                                              Wqp, bqp, Wkp, bkp, Wvp, bvp);
    k_rot<<<L, 384>>>(rot, trans);
    k_logits<<<dim3(16,16,12), dim3(32,32)>>>(w_c, w_l, gamma_h);

    const int dyn = (6144 + 1536 + 6144) * (int)sizeof(float);  // 55296 B
    cudaFuncSetAttribute(k_fused, cudaFuncAttributeMaxDynamicSharedMemorySize, dyn);
    k_fused<<<L, 512, dyn>>>(pair, Wpb, bpb, mask);

    k_av<<<dim3(24, L/32), 256>>>();
    k_pts<<<(L*96 + 255)/256, 256>>>(rot, trans);
    k_final<<<dim3(DS/32, L/32), 256>>>(Wo, bo, (float*)d_out);
}

// round 3
// speedup vs baseline: 2.6259x; 1.3469x over previous
#include <cuda_runtime.h>
#include <math.h>

#define L 512
#define DS 384
#define DP 128
#define H_ 12
#define DH 32
#define QPD 144
#define VPD 288
#define PROJD 1728
#define AVD 768
#define COMBD 2304
#define EXTD 48   /* extended logit dim per head (46 used, padded) */

// ---------------- scratch ----------------
__device__ float g_sn[L*DS];
__device__ float g_proj[L*PROJD];          // q|k|v|qp|kp|vp
__device__ float g_uq[L*H_*EXTD];          // extended query vectors
__device__ float g_wk[L*H_*EXTD];          // extended key vectors
__device__ float g_avin[L*AVD];            // v(384) | vg padded 12*32
__device__ float g_att[(size_t)H_*L*L];
__device__ float g_ptsraw[L*H_*32];
__device__ float g_comb[L*COMBD];

// ---------------- K1: LayerNorm ----------------
__global__ void k_ln(const float* __restrict__ single_, const float* __restrict__ ln_w,
                     const float* __restrict__ ln_b) {
    const int i = blockIdx.x, t = threadIdx.x;  // 384
    __shared__ float red[512];
    float x = single_[i*DS + t];
    red[t] = x;
    if (t < 128) red[384+t] = 0.f;
    __syncthreads();
    for (int s = 256; s > 0; s >>= 1) { if (t < s) red[t] += red[t+s]; __syncthreads(); }
    float mu = red[0] * (1.f/384.f);
    __syncthreads();
    float xc = x - mu;
    red[t] = xc*xc;
    if (t < 128) red[384+t] = 0.f;
    __syncthreads();
    for (int s = 256; s > 0; s >>= 1) { if (t < s) red[t] += red[t+s]; __syncthreads(); }
    float var = red[0] * (1.f/384.f);
    g_sn[i*DS + t] = xc * rsqrtf(var + 1e-5f) * ln_w[t] + ln_b[t];
}

// ---------------- K2: projection GEMM (64x64x16 tiles, 4x4/thread) ----------------
__device__ __forceinline__ void seg_of(int c, const float* Wq, const float* Wk, const float* Wv,
                                       const float* Wqp, const float* Wkp, const float* Wvp,
                                       const float** W, int* w, int* lc) {
    if (c < 384)       { *W = Wq;  *w = 384; *lc = c; }
    else if (c < 768)  { *W = Wk;  *w = 384; *lc = c-384; }
    else if (c < 1152) { *W = Wv;  *w = 384; *lc = c-768; }
    else if (c < 1296) { *W = Wqp; *w = 144; *lc = c-1152; }
    else if (c < 1440) { *W = Wkp; *w = 144; *lc = c-1296; }
    else               { *W = Wvp; *w = 288; *lc = c-1440; }
}
__device__ __forceinline__ float bias_of(int c, const float* bq, const float* bk, const float* bv,
                                         const float* bqp, const float* bkp, const float* bvp) {
    if (c < 384) return bq[c];
    if (c < 768) return bk[c-384];
    if (c < 1152) return bv[c-768];
    if (c < 1296) return bqp[c-1152];
    if (c < 1440) return bkp[c-1296];
    return bvp[c-1440];
}

__global__ void k_projgemm(const float* __restrict__ Wq, const float* __restrict__ bq,
                           const float* __restrict__ Wk, const float* __restrict__ bk,
                           const float* __restrict__ Wv, const float* __restrict__ bv,
                           const float* __restrict__ Wqp, const float* __restrict__ bqp,
                           const float* __restrict__ Wkp, const float* __restrict__ bkp,
                           const float* __restrict__ Wvp, const float* __restrict__ bvp) {
    const int n0 = blockIdx.x*64, m0 = blockIdx.y*64;
    const int t = threadIdx.x;
    const int tx = t & 15, ty = t >> 4;
    __shared__ float As[16][68], Bs[16][68];
    float acc[4][4] = {};

    const int lm = t >> 2, lk4 = (t & 3) * 4;   // As transpose load
    const int bk_ = t >> 4, bn4 = (t & 15) * 4; // Bs direct load

    for (int k0 = 0; k0 < DS; k0 += 16) {
        float4 av = *(const float4*)&g_sn[(m0+lm)*DS + k0 + lk4];
        As[lk4+0][lm] = av.x; As[lk4+1][lm] = av.y;
        As[lk4+2][lm] = av.z; As[lk4+3][lm] = av.w;
        {
            const float* W; int w, lc;
            seg_of(n0+bn4, Wq, Wk, Wv, Wqp, Wkp, Wvp, &W, &w, &lc);
            float4 bv4 = *(const float4*)&W[(k0+bk_)*w + lc];
            *(float4*)&Bs[bk_][bn4] = bv4;
        }
        __syncthreads();
        #pragma unroll
        for (int k = 0; k < 16; k++) {
            float4 a = *(const float4*)&As[k][ty*4];
            float4 b = *(const float4*)&Bs[k][tx*4];
            acc[0][0]+=a.x*b.x; acc[0][1]+=a.x*b.y; acc[0][2]+=a.x*b.z; acc[0][3]+=a.x*b.w;
            acc[1][0]+=a.y*b.x; acc[1][1]+=a.y*b.y; acc[1][2]+=a.y*b.z; acc[1][3]+=a.y*b.w;
            acc[2][0]+=a.z*b.x; acc[2][1]+=a.z*b.y; acc[2][2]+=a.z*b.z; acc[2][3]+=a.z*b.w;
            acc[3][0]+=a.w*b.x; acc[3][1]+=a.w*b.y; acc[3][2]+=a.w*b.z; acc[3][3]+=a.w*b.w;
        }
        __syncthreads();
    }
    float bb[4];
    #pragma unroll
    for (int u = 0; u < 4; u++) bb[u] = bias_of(n0+tx*4+u, bq, bk, bv, bqp, bkp, bvp);
    #pragma unroll
    for (int um = 0; um < 4; um++) {
        float4 o = make_float4(acc[um][0]+bb[0], acc[um][1]+bb[1],
                               acc[um][2]+bb[2], acc[um][3]+bb[3]);
        *(float4*)&g_proj[(size_t)(m0+ty*4+um)*PROJD + n0 + tx*4] = o;
    }
}

// ---------------- K3: rotations + avin + extended logit vectors ----------------
__global__ void k_rot(const float* __restrict__ rot, const float* __restrict__ trans,
                      const float* __restrict__ wc, const float* __restrict__ wl,
                      const float* __restrict__ gamma) {
    const int i = blockIdx.x, t = threadIdx.x;  // 384
    __shared__ float Rm[9], Tv[3];
    __shared__ float qg_s[QPD], kg_s[QPD];
    __shared__ float sq_s[H_], sk_s[H_];
    if (t < 9) Rm[t] = rot[i*9 + t];
    if (t < 3) Tv[t] = trans[i*3 + t];
    __syncthreads();
    const float* pr = &g_proj[(size_t)i*PROJD];
    if (t < QPD) {
        int i3 = t % 3, base = t - i3;
        float q0 = pr[1152+base], q1 = pr[1152+base+1], q2 = pr[1152+base+2];
        float p0 = pr[1296+base], p1 = pr[1296+base+1], p2 = pr[1296+base+2];
        qg_s[t] = Rm[i3*3+0]*q0 + Rm[i3*3+1]*q1 + Rm[i3*3+2]*q2 + Tv[i3];
        kg_s[t] = Rm[i3*3+0]*p0 + Rm[i3*3+1]*p1 + Rm[i3*3+2]*p2 + Tv[i3];
    }
    if (t < VPD) {
        int i3 = t % 3, base = t - i3;
        float v0 = pr[1440+base], v1 = pr[1440+base+1], v2 = pr[1440+base+2];
        float vg = Rm[i3*3+0]*v0 + Rm[i3*3+1]*v1 + Rm[i3*3+2]*v2 + Tv[i3];
        int h = t / 24, r = t % 24;
        g_avin[i*AVD + 384 + h*32 + r] = vg;
    }
    if (t < 96) { int h = t/8, r = t%8; g_avin[i*AVD + 384 + h*32 + 24 + r] = 0.f; }
    g_avin[i*AVD + t] = pr[768 + t];
    __syncthreads();
    if (t < H_) {
        float sq = 0.f, sk = 0.f;
        #pragma unroll
        for (int u = 0; u < 12; u++) {
            float a = qg_s[t*12+u]; sq += a*a;
            float b = kg_s[t*12+u]; sk += b*b;
        }
        sq_s[t] = sq; sk_s[t] = sk;
    }
    __syncthreads();
    const float cseq = wc[0] * rsqrtf((float)DH);
    const float wlv = wl[0];
    for (int idx = t; idx < H_*EXTD; idx += 384) {
        int h = idx / EXTD, c = idx % EXTD;
        float cg = gamma[h] * wlv;
        float uq, wk;
        if (c < 32)      { uq = pr[h*32 + c] * cseq;      wk = pr[384 + h*32 + c]; }
        else if (c < 44) { int p = c-32; uq = qg_s[h*12+p] * cg; wk = kg_s[h*12+p]; }
        else if (c == 44){ uq = -0.5f*cg*sq_s[h];          wk = 1.f; }
        else if (c == 45){ uq = 1.f;                       wk = -0.5f*cg*sk_s[h]; }
        else             { uq = 0.f;                       wk = 0.f; }
        g_uq[(size_t)i*(H_*EXTD) + idx] = uq;
        g_wk[(size_t)i*(H_*EXTD) + idx] = wk;
    }
}

// ---------------- K4: logits GEMM (U . W^T per head), 64x64, K=48 ----------------
__global__ void k_logits() {
    const int h = blockIdx.z;
    const int j0 = blockIdx.x*64, i0 = blockIdx.y*64;
    const int t = threadIdx.x;
    const int tx = t & 15, ty = t >> 4;
    __shared__ float As[16][68], Bs[16][68];
    float acc[4][4] = {};

    const int lm = t >> 2, lk4 = (t & 3) * 4;
    const int LD = H_*EXTD;

    for (int k0 = 0; k0 < EXTD; k0 += 16) {
        float4 av = *(const float4*)&g_uq[(size_t)(i0+lm)*LD + h*EXTD + k0 + lk4];
        As[lk4+0][lm] = av.x; As[lk4+1][lm] = av.y;
        As[lk4+2][lm] = av.z; As[lk4+3][lm] = av.w;
        float4 bv = *(const float4*)&g_wk[(size_t)(j0+lm)*LD + h*EXTD + k0 + lk4];
        Bs[lk4+0][lm] = bv.x; Bs[lk4+1][lm] = bv.y;
        Bs[lk4+2][lm] = bv.z; Bs[lk4+3][lm] = bv.w;
        __syncthreads();
        #pragma unroll
        for (int k = 0; k < 16; k++) {
            float4 a = *(const float4*)&As[k][ty*4];
            float4 b = *(const float4*)&Bs[k][tx*4];
            acc[0][0]+=a.x*b.x; acc[0][1]+=a.x*b.y; acc[0][2]+=a.x*b.z; acc[0][3]+=a.x*b.w;
            acc[1][0]+=a.y*b.x; acc[1][1]+=a.y*b.y; acc[1][2]+=a.y*b.z; acc[1][3]+=a.y*b.w;
            acc[2][0]+=a.z*b.x; acc[2][1]+=a.z*b.y; acc[2][2]+=a.z*b.z; acc[2][3]+=a.z*b.w;
            acc[3][0]+=a.w*b.x; acc[3][1]+=a.w*b.y; acc[3][2]+=a.w*b.z; acc[3][3]+=a.w*b.w;
        }
        __syncthreads();
    }
    #pragma unroll
    for (int um = 0; um < 4; um++) {
        float4 o = make_float4(acc[um][0], acc[um][1], acc[um][2], acc[um][3]);
        *(float4*)&g_att[((size_t)h*L + (i0+ty*4+um))*L + j0 + tx*4] = o;
    }
}

// ---------------- K5: fused pair-bias + softmax + pair_out ----------------
__global__ void k_fused(const float* __restrict__ pair, const float* __restrict__ Wpb,
                        const float* __restrict__ bpb, const float* __restrict__ mask) {
    extern __shared__ float sm[];
    float* lg    = sm;          // 6144
    float* wpb_s = sm + 6144;   // 1536
    float* part  = sm + 7680;   // 6144
    __shared__ float bpb_s[H_];

    const int i = blockIdx.x;
    const int t = threadIdx.x;  // 512

    for (int idx = t; idx < DP*H_; idx += 512) wpb_s[idx] = Wpb[idx];
    if (t < H_) bpb_s[t] = bpb[t];
    for (int idx = t; idx < H_*L; idx += 512) {
        int h = idx >> 9, j = idx & 511;
        lg[idx] = g_att[((size_t)h*L + i)*L + j];
    }
    __syncthreads();

    {
        const int j = t;
        const float4* pr = (const float4*)(pair + ((size_t)i*L + j)*DP);
        float acc[H_];
        #pragma unroll
        for (int h = 0; h < H_; h++) acc[h] = bpb_s[h];
        #pragma unroll 4
        for (int c4 = 0; c4 < 32; c4++) {
            float4 p = pr[c4];
            const float* w0 = &wpb_s[c4*48];
            #pragma unroll
            for (int h = 0; h < H_; h++)
                acc[h] += p.x*w0[h] + p.y*w0[12+h] + p.z*w0[24+h] + p.w*w0[36+h];
        }
        float mv = mask[i] * mask[j];
        #pragma unroll
        for (int h = 0; h < H_; h++) {
            float v2 = lg[h*L + j] + acc[h];
            lg[h*L + j] = (mv > 0.f) ? v2 : -1e9f;
        }
    }
    __syncthreads();

    {
        const int w = t >> 5, lane = t & 31;
        if (w < H_) {
            float* row = &lg[w*L];
            float m = -1e30f;
            for (int j = lane; j < L; j += 32) m = fmaxf(m, row[j]);
            #pragma unroll
            for (int o = 16; o; o >>= 1) m = fmaxf(m, __shfl_xor_sync(0xffffffffu, m, o));
            float s = 0.f;
            for (int j = lane; j < L; j += 32) { float e = __expf(row[j]-m); row[j] = e; s += e; }
            #pragma unroll
            for (int o = 16; o; o >>= 1) s += __shfl_xor_sync(0xffffffffu, s, o);
            float inv = 1.f / s;
            for (int j = lane; j < L; j += 32) {
                float a = row[j] * inv;
                row[j] = a;
                g_att[((size_t)w*L + i)*L + j] = a;
            }
        }
    }
    __syncthreads();

    {
        const int g = t >> 7, c = t & 127;
        float acc[H_] = {};
        const float* prow = pair + ((size_t)i*L + g*128)*DP + c;
        const float* lgj = &lg[g*128];
        #pragma unroll 2
        for (int jj = 0; jj < 128; jj++) {
            float p = prow[(size_t)jj*DP];
            #pragma unroll
            for (int h = 0; h < H_; h++) acc[h] += lgj[h*L + jj] * p;
        }
        #pragma unroll
        for (int h = 0; h < H_; h++) part[g*1536 + h*DP + c] = acc[h];
    }
    __syncthreads();
    for (int idx = t; idx < 1536; idx += 512)
        g_comb[(size_t)i*COMBD + 768 + idx] =
            part[idx] + part[1536+idx] + part[3072+idx] + part[4608+idx];
}

// ---------------- K6: attn @ [v|vg] per head, 64x64 GEMM, K=512 ----------------
__global__ void k_av() {
    const int h = blockIdx.x;             // 0..11
    const int m0 = blockIdx.y*64;
    const int t = threadIdx.x;
    const int tx = t & 15, ty = t >> 4;
    __shared__ float As[16][68], Bs[16][68];
    float acc[4][4] = {};

    const int lm = t >> 2, lk4 = (t & 3) * 4;
    const int bk_ = t >> 4, bn4 = (t & 15) * 4;
    const int bcol = (bn4 < 32) ? (h*32 + bn4) : (384 + h*32 + bn4 - 32);

    for (int k0 = 0; k0 < L; k0 += 16) {
        float4 av = *(const float4*)&g_att[((size_t)h*L + m0+lm)*L + k0 + lk4];
        As[lk4+0][lm] = av.x; As[lk4+1][lm] = av.y;
        As[lk4+2][lm] = av.z; As[lk4+3][lm] = av.w;
        *(float4*)&Bs[bk_][bn4] = *(const float4*)&g_avin[(k0+bk_)*AVD + bcol];
        __syncthreads();
        #pragma unroll
        for (int k = 0; k < 16; k++) {
            float4 a = *(const float4*)&As[k][ty*4];
            float4 b = *(const float4*)&Bs[k][tx*4];
            acc[0][0]+=a.x*b.x; acc[0][1]+=a.x*b.y; acc[0][2]+=a.x*b.z; acc[0][3]+=a.x*b.w;
            acc[1][0]+=a.y*b.x; acc[1][1]+=a.y*b.y; acc[1][2]+=a.y*b.z; acc[1][3]+=a.y*b.w;
            acc[2][0]+=a.z*b.x; acc[2][1]+=a.z*b.y; acc[2][2]+=a.z*b.z; acc[2][3]+=a.z*b.w;
            acc[3][0]+=a.w*b.x; acc[3][1]+=a.w*b.y; acc[3][2]+=a.w*b.z; acc[3][3]+=a.w*b.w;
        }
        __syncthreads();
    }
    #pragma unroll
    for (int um = 0; um < 4; um++) {
        float4 o = make_float4(acc[um][0], acc[um][1], acc[um][2], acc[um][3]);
        if (tx*4 < 32)
            *(float4*)&g_comb[(size_t)(m0+ty*4+um)*COMBD + h*32 + tx*4] = o;
        else
            *(float4*)&g_ptsraw[(m0+ty*4+um)*384 + h*32 + tx*4 - 32] = o;
    }
}

// ---------------- K7: point frame transform + norm ----------------
__global__ void k_pts(const float* __restrict__ rot, const float* __restrict__ trans) {
    int idx = blockIdx.x*256 + threadIdx.x;
    if (idx >= L*96) return;
    int i = idx / 96, u = idx % 96;
    int h = u >> 3, p = u & 7;
    const float* src = &g_ptsraw[i*384 + h*32 + p*3];
    float T0 = trans[i*3+0], T1 = trans[i*3+1], T2 = trans[i*3+2];
    float px = src[0]-T0, py = src[1]-T1, pz = src[2]-T2;
    const float* R = &rot[i*9];
    float lx = R[0]*px + R[3]*py + R[6]*pz;
    float ly = R[1]*px + R[4]*py + R[7]*pz;
    float lz = R[2]*px + R[5]*py + R[8]*pz;
    float nrm = sqrtf(lx*lx + ly*ly + lz*lz);
    float* dst = &g_comb[(size_t)i*COMBD + 384 + u*4];
    dst[0] = nrm; dst[1] = lx; dst[2] = ly; dst[3] = lz;
}

// ---------------- K8: combined @ Wo + bo (64x64 tiles) ----------------
__global__ void k_final(const float* __restrict__ Wo, const float* __restrict__ bo,
                        float* __restrict__ out) {
    const int n0 = blockIdx.x*64, m0 = blockIdx.y*64;
    const int t = threadIdx.x;
    const int tx = t & 15, ty = t >> 4;
    __shared__ float As[16][68], Bs[16][68];
    float acc[4][4] = {};

    const int lm = t >> 2, lk4 = (t & 3) * 4;
    const int bk_ = t >> 4, bn4 = (t & 15) * 4;

    for (int k0 = 0; k0 < COMBD; k0 += 16) {
        float4 av = *(const float4*)&g_comb[(size_t)(m0+lm)*COMBD + k0 + lk4];
        As[lk4+0][lm] = av.x; As[lk4+1][lm] = av.y;
        As[lk4+2][lm] = av.z; As[lk4+3][lm] = av.w;
        *(float4*)&Bs[bk_][bn4] = *(const float4*)&Wo[(size_t)(k0+bk_)*DS + n0 + bn4];
        __syncthreads();
        #pragma unroll
        for (int k = 0; k < 16; k++) {
            float4 a = *(const float4*)&As[k][ty*4];
            float4 b = *(const float4*)&Bs[k][tx*4];
            acc[0][0]+=a.x*b.x; acc[0][1]+=a.x*b.y; acc[0][2]+=a.x*b.z; acc[0][3]+=a.x*b.w;
            acc[1][0]+=a.y*b.x; acc[1][1]+=a.y*b.y; acc[1][2]+=a.y*b.z; acc[1][3]+=a.y*b.w;
            acc[2][0]+=a.z*b.x; acc[2][1]+=a.z*b.y; acc[2][2]+=a.z*b.z; acc[2][3]+=a.z*b.w;
            acc[3][0]+=a.w*b.x; acc[3][1]+=a.w*b.y; acc[3][2]+=a.w*b.z; acc[3][3]+=a.w*b.w;
        }
        __syncthreads();
    }
    float4 bb = *(const float4*)&bo[n0 + tx*4];
    #pragma unroll
    for (int um = 0; um < 4; um++) {
        float4 o = make_float4(acc[um][0]+bb.x, acc[um][1]+bb.y,
                               acc[um][2]+bb.z, acc[um][3]+bb.w);
        *(float4*)&out[(size_t)(m0+ty*4+um)*DS + n0 + tx*4] = o;
    }
}

// ---------------- launch ----------------
extern "C" void kernel_launch(void* const* d_in, const int* in_sizes, int n_in,
                              void* d_out, int out_size) {
    const float* single_ = (const float*)d_in[0];
    const float* pair    = (const float*)d_in[1];
    const float* rot     = (const float*)d_in[2];
    const float* trans   = (const float*)d_in[3];
    const float* mask    = (const float*)d_in[4];
    const float* ln_w    = (const float*)d_in[5];
    const float* ln_b    = (const float*)d_in[6];
    const float* Wq      = (const float*)d_in[7];
    const float* bq      = (const float*)d_in[8];
    const float* Wk      = (const float*)d_in[9];
    const float* bk      = (const float*)d_in[10];
    const float* Wv      = (const float*)d_in[11];
    const float* bv      = (const float*)d_in[12];
    const float* Wqp     = (const float*)d_in[13];
    const float* bqp     = (const float*)d_in[14];
    const float* Wkp     = (const float*)d_in[15];
    const float* bkp     = (const float*)d_in[16];
    const float* Wvp     = (const float*)d_in[17];
    const float* bvp     = (const float*)d_in[18];
    const float* Wpb     = (const float*)d_in[19];
    const float* bpb     = (const float*)d_in[20];
    const float* Wo      = (const float*)d_in[21];
    const float* bo      = (const float*)d_in[22];
    const float* w_c     = (const float*)d_in[23];
    const float* w_l     = (const float*)d_in[24];
    const float* gamma_h = (const float*)d_in[25];

    k_ln<<<L, 384>>>(single_, ln_w, ln_b);
    k_projgemm<<<dim3(PROJD/64, L/64), 256>>>(Wq, bq, Wk, bk, Wv, bv,
                                              Wqp, bqp, Wkp, bkp, Wvp, bvp);
    k_rot<<<L, 384>>>(rot, trans, w_c, w_l, gamma_h);
    k_logits<<<dim3(L/64, L/64, H_), 256>>>();

    const int dyn = (6144 + 1536 + 6144) * (int)sizeof(float);
    cudaFuncSetAttribute(k_fused, cudaFuncAttributeMaxDynamicSharedMemorySize, dyn);
    k_fused<<<L, 512, dyn>>>(pair, Wpb, bpb, mask);

    k_av<<<dim3(H_, L/64), 256>>>();
    k_pts<<<(L*96 + 255)/256, 256>>>(rot, trans);
    k_final<<<dim3(DS/64, L/64), 256>>>(Wo, bo, (float*)d_out);
}

// round 4
// speedup vs baseline: 2.9414x; 1.1201x over previous
#include <cuda_runtime.h>
#include <math.h>

#define L 512
#define DS 384
#define DP 128
#define H_ 12
#define DH 32
#define QPD 144
#define VPD 288
#define PROJD 1728
#define AVD 768
#define COMBD 2304
#define EXTD 48
#define LGS 516   /* lg row stride */
#define ATS 18    /* att_t row stride */
#define PTS 132   /* pair tile row stride */

// ---------------- scratch ----------------
__device__ float g_sn[L*DS];
__device__ float g_proj[L*PROJD];
__device__ float g_uq[L*H_*EXTD];
__device__ float g_wk[L*H_*EXTD];
__device__ float g_avin[L*AVD];
__device__ float g_att[(size_t)H_*L*L];
__device__ float g_ptsraw[L*H_*32];
__device__ float g_comb[L*COMBD];
__device__ float g_fpart[4*L*DS];

// ---------------- K1: LayerNorm ----------------
__global__ void k_ln(const float* __restrict__ single_, const float* __restrict__ ln_w,
                     const float* __restrict__ ln_b) {
    const int i = blockIdx.x, t = threadIdx.x;  // 384
    __shared__ float red[512];
    float x = single_[i*DS + t];
    red[t] = x;
    if (t < 128) red[384+t] = 0.f;
    __syncthreads();
    for (int s = 256; s > 0; s >>= 1) { if (t < s) red[t] += red[t+s]; __syncthreads(); }
    float mu = red[0] * (1.f/384.f);
    __syncthreads();
    float xc = x - mu;
    red[t] = xc*xc;
    if (t < 128) red[384+t] = 0.f;
    __syncthreads();
    for (int s = 256; s > 0; s >>= 1) { if (t < s) red[t] += red[t+s]; __syncthreads(); }
    float var = red[0] * (1.f/384.f);
    g_sn[i*DS + t] = xc * rsqrtf(var + 1e-5f) * ln_w[t] + ln_b[t];
}

// ---------------- K2: projection GEMM ----------------
__device__ __forceinline__ void seg_of(int c, const float* Wq, const float* Wk, const float* Wv,
                                       const float* Wqp, const float* Wkp, const float* Wvp,
                                       const float** W, int* w, int* lc) {
    if (c < 384)       { *W = Wq;  *w = 384; *lc = c; }
    else if (c < 768)  { *W = Wk;  *w = 384; *lc = c-384; }
    else if (c < 1152) { *W = Wv;  *w = 384; *lc = c-768; }
    else if (c < 1296) { *W = Wqp; *w = 144; *lc = c-1152; }
    else if (c < 1440) { *W = Wkp; *w = 144; *lc = c-1296; }
    else               { *W = Wvp; *w = 288; *lc = c-1440; }
}
__device__ __forceinline__ float bias_of(int c, const float* bq, const float* bk, const float* bv,
                                         const float* bqp, const float* bkp, const float* bvp) {
    if (c < 384) return bq[c];
    if (c < 768) return bk[c-384];
    if (c < 1152) return bv[c-768];
    if (c < 1296) return bqp[c-1152];
    if (c < 1440) return bkp[c-1296];
    return bvp[c-1440];
}

__global__ void k_projgemm(const float* __restrict__ Wq, const float* __restrict__ bq,
                           const float* __restrict__ Wk, const float* __restrict__ bk,
                           const float* __restrict__ Wv, const float* __restrict__ bv,
                           const float* __restrict__ Wqp, const float* __restrict__ bqp,
                           const float* __restrict__ Wkp, const float* __restrict__ bkp,
                           const float* __restrict__ Wvp, const float* __restrict__ bvp) {
    const int n0 = blockIdx.x*64, m0 = blockIdx.y*64;
    const int t = threadIdx.x;
    const int tx = t & 15, ty = t >> 4;
    __shared__ float As[16][68], Bs[16][68];
    float acc[4][4] = {};

    const int lm = t >> 2, lk4 = (t & 3) * 4;
    const int bk_ = t >> 4, bn4 = (t & 15) * 4;

    for (int k0 = 0; k0 < DS; k0 += 16) {
        float4 av = *(const float4*)&g_sn[(m0+lm)*DS + k0 + lk4];
        As[lk4+0][lm] = av.x; As[lk4+1][lm] = av.y;
        As[lk4+2][lm] = av.z; As[lk4+3][lm] = av.w;
        {
            const float* W; int w, lc;
            seg_of(n0+bn4, Wq, Wk, Wv, Wqp, Wkp, Wvp, &W, &w, &lc);
            *(float4*)&Bs[bk_][bn4] = *(const float4*)&W[(k0+bk_)*w + lc];
        }
        __syncthreads();
        #pragma unroll
        for (int k = 0; k < 16; k++) {
            float4 a = *(const float4*)&As[k][ty*4];
            float4 b = *(const float4*)&Bs[k][tx*4];
            acc[0][0]+=a.x*b.x; acc[0][1]+=a.x*b.y; acc[0][2]+=a.x*b.z; acc[0][3]+=a.x*b.w;
            acc[1][0]+=a.y*b.x; acc[1][1]+=a.y*b.y; acc[1][2]+=a.y*b.z; acc[1][3]+=a.y*b.w;
            acc[2][0]+=a.z*b.x; acc[2][1]+=a.z*b.y; acc[2][2]+=a.z*b.z; acc[2][3]+=a.z*b.w;
            acc[3][0]+=a.w*b.x; acc[3][1]+=a.w*b.y; acc[3][2]+=a.w*b.z; acc[3][3]+=a.w*b.w;
        }
        __syncthreads();
    }
    float bb[4];
    #pragma unroll
    for (int u = 0; u < 4; u++) bb[u] = bias_of(n0+tx*4+u, bq, bk, bv, bqp, bkp, bvp);
    #pragma unroll
    for (int um = 0; um < 4; um++) {
        float4 o = make_float4(acc[um][0]+bb[0], acc[um][1]+bb[1],
                               acc[um][2]+bb[2], acc[um][3]+bb[3]);
        *(float4*)&g_proj[(size_t)(m0+ty*4+um)*PROJD + n0 + tx*4] = o;
    }
}

// ---------------- K3: rotations + avin + extended vectors ----------------
__global__ void k_rot(const float* __restrict__ rot, const float* __restrict__ trans,
                      const float* __restrict__ wc, const float* __restrict__ wl,
                      const float* __restrict__ gamma) {
    const int i = blockIdx.x, t = threadIdx.x;  // 384
    __shared__ float Rm[9], Tv[3];
    __shared__ float qg_s[QPD], kg_s[QPD];
    __shared__ float sq_s[H_], sk_s[H_];
    if (t < 9) Rm[t] = rot[i*9 + t];
    if (t < 3) Tv[t] = trans[i*3 + t];
    __syncthreads();
    const float* pr = &g_proj[(size_t)i*PROJD];
    if (t < QPD) {
        int i3 = t % 3, base = t - i3;
        float q0 = pr[1152+base], q1 = pr[1152+base+1], q2 = pr[1152+base+2];
        float p0 = pr[1296+base], p1 = pr[1296+base+1], p2 = pr[1296+base+2];
        qg_s[t] = Rm[i3*3+0]*q0 + Rm[i3*3+1]*q1 + Rm[i3*3+2]*q2 + Tv[i3];
        kg_s[t] = Rm[i3*3+0]*p0 + Rm[i3*3+1]*p1 + Rm[i3*3+2]*p2 + Tv[i3];
    }
    if (t < VPD) {
        int i3 = t % 3, base = t - i3;
        float v0 = pr[1440+base], v1 = pr[1440+base+1], v2 = pr[1440+base+2];
        float vg = Rm[i3*3+0]*v0 + Rm[i3*3+1]*v1 + Rm[i3*3+2]*v2 + Tv[i3];
        int h = t / 24, r = t % 24;
        g_avin[i*AVD + 384 + h*32 + r] = vg;
    }
    if (t < 96) { int h = t/8, r = t%8; g_avin[i*AVD + 384 + h*32 + 24 + r] = 0.f; }
    g_avin[i*AVD + t] = pr[768 + t];
    __syncthreads();
    if (t < H_) {
        float sq = 0.f, sk = 0.f;
        #pragma unroll
        for (int u = 0; u < 12; u++) {
            float a = qg_s[t*12+u]; sq += a*a;
            float b = kg_s[t*12+u]; sk += b*b;
        }
        sq_s[t] = sq; sk_s[t] = sk;
    }
    __syncthreads();
    const float cseq = wc[0] * rsqrtf((float)DH);
    const float wlv = wl[0];
    for (int idx = t; idx < H_*EXTD; idx += 384) {
        int h = idx / EXTD, c = idx % EXTD;
        float cg = gamma[h] * wlv;
        float uq, wk;
        if (c < 32)      { uq = pr[h*32 + c] * cseq;      wk = pr[384 + h*32 + c]; }
        else if (c < 44) { int p = c-32; uq = qg_s[h*12+p] * cg; wk = kg_s[h*12+p]; }
        else if (c == 44){ uq = -0.5f*cg*sq_s[h];          wk = 1.f; }
        else if (c == 45){ uq = 1.f;                       wk = -0.5f*cg*sk_s[h]; }
        else             { uq = 0.f;                       wk = 0.f; }
        g_uq[(size_t)i*(H_*EXTD) + idx] = uq;
        g_wk[(size_t)i*(H_*EXTD) + idx] = wk;
    }
}

// ---------------- K4: logits GEMM, single-stage K=48 ----------------
__global__ void k_logits() {
    const int h = blockIdx.z;
    const int j0 = blockIdx.x*64, i0 = blockIdx.y*64;
    const int t = threadIdx.x;
    const int tx = t & 15, ty = t >> 4;
    __shared__ float Us[48][68], Ws[48][68];
    float acc[4][4] = {};
    const int LD = H_*EXTD;

    for (int f = t; f < 768; f += 256) {
        int m = f / 12, k4 = (f % 12) * 4;
        float4 u = *(const float4*)&g_uq[(size_t)(i0+m)*LD + h*EXTD + k4];
        Us[k4+0][m]=u.x; Us[k4+1][m]=u.y; Us[k4+2][m]=u.z; Us[k4+3][m]=u.w;
        float4 w = *(const float4*)&g_wk[(size_t)(j0+m)*LD + h*EXTD + k4];
        Ws[k4+0][m]=w.x; Ws[k4+1][m]=w.y; Ws[k4+2][m]=w.z; Ws[k4+3][m]=w.w;
    }
    __syncthreads();
    #pragma unroll
    for (int k = 0; k < 48; k++) {
        float4 a = *(const float4*)&Us[k][ty*4];
        float4 b = *(const float4*)&Ws[k][tx*4];
        acc[0][0]+=a.x*b.x; acc[0][1]+=a.x*b.y; acc[0][2]+=a.x*b.z; acc[0][3]+=a.x*b.w;
        acc[1][0]+=a.y*b.x; acc[1][1]+=a.y*b.y; acc[1][2]+=a.y*b.z; acc[1][3]+=a.y*b.w;
        acc[2][0]+=a.z*b.x; acc[2][1]+=a.z*b.y; acc[2][2]+=a.z*b.z; acc[2][3]+=a.z*b.w;
        acc[3][0]+=a.w*b.x; acc[3][1]+=a.w*b.y; acc[3][2]+=a.w*b.z; acc[3][3]+=a.w*b.w;
    }
    #pragma unroll
    for (int um = 0; um < 4; um++) {
        float4 o = make_float4(acc[um][0], acc[um][1], acc[um][2], acc[um][3]);
        *(float4*)&g_att[((size_t)h*L + (i0+ty*4+um))*L + j0 + tx*4] = o;
    }
}

// ---------------- K5: fused pair-bias + softmax + pair_out (GEMM phases) ------
__global__ void k_fused(const float* __restrict__ pair, const float* __restrict__ Wpb,
                        const float* __restrict__ bpb, const float* __restrict__ mask) {
    extern __shared__ float sm[];
    float* wpb_s  = sm;                       // 128*16 = 2048
    float* lg     = sm + 2048;                // 12*516 = 6192
    float* att_t  = sm + 2048 + 6192;         // 512*18 = 9216
    float* ptile  = sm + 2048 + 6192 + 9216;  // 64*132 = 8448
    float* mask_s = sm + 2048 + 6192 + 9216 + 8448;  // 512
    __shared__ float bpb_s[H_];

    const int i = blockIdx.x;
    const int t = threadIdx.x;  // 256

    // init
    for (int idx = t; idx < 2048; idx += 256) {
        int c = idx >> 4, h = idx & 15;
        wpb_s[idx] = (h < 12) ? Wpb[c*12 + h] : 0.f;
    }
    if (t < H_) bpb_s[t] = bpb[t];
    for (int idx = t; idx < 512; idx += 256) mask_s[idx] = mask[idx];
    for (int idx = t; idx < 512*6; idx += 256) {
        int j = idx / 6, c = 12 + idx % 6;
        att_t[j*ATS + c] = 0.f;
    }
    __syncthreads();
    for (int idx = t; idx < H_*L; idx += 256) {
        int h = idx >> 9, j = idx & 511;
        lg[h*LGS + j] = g_att[((size_t)h*L + i)*L + j] + bpb_s[h];
    }

    // ---- phase 1: bias GEMM over 8 pair tiles ----
    const int pj = t >> 2;   // 0..63
    const int hq = t & 3;    // 0..3 (hq 3 is padding)
    for (int tile = 0; tile < 8; tile++) {
        __syncthreads();
        const int j0 = tile*64;
        for (int f = t; f < 2048; f += 256) {
            int r = f >> 5, c4 = (f & 31) * 4;
            *(float4*)&ptile[r*PTS + c4] =
                *(const float4*)&pair[(((size_t)i*L) + j0 + r)*DP + c4];
        }
        __syncthreads();
        float a0=0.f, a1=0.f, a2=0.f, a3=0.f;
        const float* prow = &ptile[pj*PTS];
        #pragma unroll 8
        for (int c = 0; c < 128; c += 4) {
            float4 p  = *(const float4*)&prow[c];
            float4 w0 = *(const float4*)&wpb_s[(c+0)*16 + hq*4];
            float4 w1 = *(const float4*)&wpb_s[(c+1)*16 + hq*4];
            float4 w2 = *(const float4*)&wpb_s[(c+2)*16 + hq*4];
            float4 w3 = *(const float4*)&wpb_s[(c+3)*16 + hq*4];
            a0 += p.x*w0.x + p.y*w1.x + p.z*w2.x + p.w*w3.x;
            a1 += p.x*w0.y + p.y*w1.y + p.z*w2.y + p.w*w3.y;
            a2 += p.x*w0.z + p.y*w1.z + p.z*w2.z + p.w*w3.z;
            a3 += p.x*w0.w + p.y*w1.w + p.z*w2.w + p.w*w3.w;
        }
        if (hq < 3) {
            lg[(hq*4+0)*LGS + j0+pj] += a0;
            lg[(hq*4+1)*LGS + j0+pj] += a1;
            lg[(hq*4+2)*LGS + j0+pj] += a2;
            lg[(hq*4+3)*LGS + j0+pj] += a3;
        }
    }
    __syncthreads();

    // ---- mask ----
    const float mi = mask[i];
    for (int idx = t; idx < H_*L; idx += 256) {
        int h = idx >> 9, j = idx & 511;
        if (mi * mask_s[j] <= 0.f) lg[h*LGS + j] = -1e9f;
    }
    __syncthreads();

    // ---- softmax: warp per head ----
    {
        const int w = t >> 5, lane = t & 31;  // 8 warps
        for (int h = w; h < H_; h += 8) {
            float* row = &lg[h*LGS];
            float m = -1e30f;
            for (int j = lane; j < L; j += 32) m = fmaxf(m, row[j]);
            #pragma unroll
            for (int o = 16; o; o >>= 1) m = fmaxf(m, __shfl_xor_sync(0xffffffffu, m, o));
            float s = 0.f;
            for (int j = lane; j < L; j += 32) { float e = __expf(row[j]-m); row[j] = e; s += e; }
            #pragma unroll
            for (int o = 16; o; o >>= 1) s += __shfl_xor_sync(0xffffffffu, s, o);
            float inv = 1.f / s;
            for (int j = lane; j < L; j += 32) {
                float a = row[j] * inv;
                g_att[((size_t)h*L + i)*L + j] = a;
                att_t[j*ATS + h] = a;
            }
        }
    }

    // ---- phase 3: pair_out GEMM (att_t^T @ pair), acc[2][4] ----
    const int th = t >> 5;   // 0..7  (h pair)
    const int tc = t & 31;   // 0..31 (c quad)
    float acc[2][4] = {};
    for (int tile = 0; tile < 8; tile++) {
        __syncthreads();
        const int j0 = tile*64;
        for (int f = t; f < 2048; f += 256) {
            int r = f >> 5, c4 = (f & 31) * 4;
            *(float4*)&ptile[r*PTS + c4] =
                *(const float4*)&pair[(((size_t)i*L) + j0 + r)*DP + c4];
        }
        __syncthreads();
        #pragma unroll 4
        for (int jj = 0; jj < 64; jj++) {
            float2 a = *(const float2*)&att_t[(j0+jj)*ATS + th*2];
            float4 b = *(const float4*)&ptile[jj*PTS + tc*4];
            acc[0][0]+=a.x*b.x; acc[0][1]+=a.x*b.y; acc[0][2]+=a.x*b.z; acc[0][3]+=a.x*b.w;
            acc[1][0]+=a.y*b.x; acc[1][1]+=a.y*b.y; acc[1][2]+=a.y*b.z; acc[1][3]+=a.y*b.w;
        }
    }
    #pragma unroll
    for (int u = 0; u < 2; u++) {
        int h = th*2 + u;
        if (h < H_) {
            float4 o = make_float4(acc[u][0], acc[u][1], acc[u][2], acc[u][3]);
            *(float4*)&g_comb[(size_t)i*COMBD + 768 + h*DP + tc*4] = o;
        }
    }
}

// ---------------- K6: attn @ [v|vg] per head ----------------
__global__ void k_av() {
    const int h = blockIdx.x;
    const int m0 = blockIdx.y*64;
    const int t = threadIdx.x;
    const int tx = t & 15, ty = t >> 4;
    __shared__ float As[16][68], Bs[16][68];
    float acc[4][4] = {};

    const int lm = t >> 2, lk4 = (t & 3) * 4;
    const int bk_ = t >> 4, bn4 = (t & 15) * 4;
    const int bcol = (bn4 < 32) ? (h*32 + bn4) : (384 + h*32 + bn4 - 32);

    for (int k0 = 0; k0 < L; k0 += 16) {
        float4 av = *(const float4*)&g_att[((size_t)h*L + m0+lm)*L + k0 + lk4];
        As[lk4+0][lm] = av.x; As[lk4+1][lm] = av.y;
        As[lk4+2][lm] = av.z; As[lk4+3][lm] = av.w;
        *(float4*)&Bs[bk_][bn4] = *(const float4*)&g_avin[(k0+bk_)*AVD + bcol];
        __syncthreads();
        #pragma unroll
        for (int k = 0; k < 16; k++) {
            float4 a = *(const float4*)&As[k][ty*4];
            float4 b = *(const float4*)&Bs[k][tx*4];
            acc[0][0]+=a.x*b.x; acc[0][1]+=a.x*b.y; acc[0][2]+=a.x*b.z; acc[0][3]+=a.x*b.w;
            acc[1][0]+=a.y*b.x; acc[1][1]+=a.y*b.y; acc[1][2]+=a.y*b.z; acc[1][3]+=a.y*b.w;
            acc[2][0]+=a.z*b.x; acc[2][1]+=a.z*b.y; acc[2][2]+=a.z*b.z; acc[2][3]+=a.z*b.w;
            acc[3][0]+=a.w*b.x; acc[3][1]+=a.w*b.y; acc[3][2]+=a.w*b.z; acc[3][3]+=a.w*b.w;
        }
        __syncthreads();
    }
    #pragma unroll
    for (int um = 0; um < 4; um++) {
        float4 o = make_float4(acc[um][0], acc[um][1], acc[um][2], acc[um][3]);
        if (tx*4 < 32)
            *(float4*)&g_comb[(size_t)(m0+ty*4+um)*COMBD + h*32 + tx*4] = o;
        else
            *(float4*)&g_ptsraw[(m0+ty*4+um)*384 + h*32 + tx*4 - 32] = o;
    }
}

// ---------------- K7: point frame transform + norm ----------------
__global__ void k_pts(const float* __restrict__ rot, const float* __restrict__ trans) {
    int idx = blockIdx.x*256 + threadIdx.x;
    if (idx >= L*96) return;
    int i = idx / 96, u = idx % 96;
    int h = u >> 3, p = u & 7;
    const float* src = &g_ptsraw[i*384 + h*32 + p*3];
    float T0 = trans[i*3+0], T1 = trans[i*3+1], T2 = trans[i*3+2];
    float px = src[0]-T0, py = src[1]-T1, pz = src[2]-T2;
    const float* R = &rot[i*9];
    float lx = R[0]*px + R[3]*py + R[6]*pz;
    float ly = R[1]*px + R[4]*py + R[7]*pz;
    float lz = R[2]*px + R[5]*py + R[8]*pz;
    float nrm = sqrtf(lx*lx + ly*ly + lz*lz);
    float* dst = &g_comb[(size_t)i*COMBD + 384 + u*4];
    dst[0] = nrm; dst[1] = lx; dst[2] = ly; dst[3] = lz;
}

// ---------------- K8: combined @ Wo, split-K=4 ----------------
__global__ void k_final4(const float* __restrict__ Wo) {
    const int kc = blockIdx.z;                 // 0..3
    const int n0 = blockIdx.x*64, m0 = blockIdx.y*64;
    const int t = threadIdx.x;
    const int tx = t & 15, ty = t >> 4;
    __shared__ float As[16][68], Bs[16][68];
    float acc[4][4] = {};

    const int lm = t >> 2, lk4 = (t & 3) * 4;
    const int bk_ = t >> 4, bn4 = (t & 15) * 4;

    const int kbeg = kc*576, kend = kbeg + 576;
    for (int k0 = kbeg; k0 < kend; k0 += 16) {
        float4 av = *(const float4*)&g_comb[(size_t)(m0+lm)*COMBD + k0 + lk4];
        As[lk4+0][lm] = av.x; As[lk4+1][lm] = av.y;
        As[lk4+2][lm] = av.z; As[lk4+3][lm] = av.w;
        *(float4*)&Bs[bk_][bn4] = *(const float4*)&Wo[(size_t)(k0+bk_)*DS + n0 + bn4];
        __syncthreads();
        #pragma unroll
        for (int k = 0; k < 16; k++) {
            float4 a = *(const float4*)&As[k][ty*4];
            float4 b = *(const float4*)&Bs[k][tx*4];
            acc[0][0]+=a.x*b.x; acc[0][1]+=a.x*b.y; acc[0][2]+=a.x*b.z; acc[0][3]+=a.x*b.w;
            acc[1][0]+=a.y*b.x; acc[1][1]+=a.y*b.y; acc[1][2]+=a.y*b.z; acc[1][3]+=a.y*b.w;
            acc[2][0]+=a.z*b.x; acc[2][1]+=a.z*b.y; acc[2][2]+=a.z*b.z; acc[2][3]+=a.z*b.w;
            acc[3][0]+=a.w*b.x; acc[3][1]+=a.w*b.y; acc[3][2]+=a.w*b.z; acc[3][3]+=a.w*b.w;
        }
        __syncthreads();
    }
    #pragma unroll
    for (int um = 0; um < 4; um++) {
        float4 o = make_float4(acc[um][0], acc[um][1], acc[um][2], acc[um][3]);
        *(float4*)&g_fpart[((size_t)kc*L + m0+ty*4+um)*DS + n0 + tx*4] = o;
    }
}

__global__ void k_fred(const float* __restrict__ bo, float* __restrict__ out) {
    int f = blockIdx.x*256 + threadIdx.x;   // float4 index, 49152 total
    int n = (f*4) % DS;
    float4 p0 = *(const float4*)&g_fpart[(size_t)0*L*DS + f*4];
    float4 p1 = *(const float4*)&g_fpart[(size_t)1*L*DS + f*4];
    float4 p2 = *(const float4*)&g_fpart[(size_t)2*L*DS + f*4];
    float4 p3 = *(const float4*)&g_fpart[(size_t)3*L*DS + f*4];
    float4 bb = *(const float4*)&bo[n];
    float4 o = make_float4(p0.x+p1.x+p2.x+p3.x+bb.x, p0.y+p1.y+p2.y+p3.y+bb.y,
                           p0.z+p1.z+p2.z+p3.z+bb.z, p0.w+p1.w+p2.w+p3.w+bb.w);
    *(float4*)&out[f*4] = o;
}

// ---------------- launch ----------------
extern "C" void kernel_launch(void* const* d_in, const int* in_sizes, int n_in,
                              void* d_out, int out_size) {
    const float* single_ = (const float*)d_in[0];
    const float* pair    = (const float*)d_in[1];
    const float* rot     = (const float*)d_in[2];
    const float* trans   = (const float*)d_in[3];
    const float* mask    = (const float*)d_in[4];
    const float* ln_w    = (const float*)d_in[5];
    const float* ln_b    = (const float*)d_in[6];
    const float* Wq      = (const float*)d_in[7];
    const float* bq      = (const float*)d_in[8];
    const float* Wk      = (const float*)d_in[9];
    const float* bk      = (const float*)d_in[10];
    const float* Wv      = (const float*)d_in[11];
    const float* bv      = (const float*)d_in[12];
    const float* Wqp     = (const float*)d_in[13];
    const float* bqp     = (const float*)d_in[14];
    const float* Wkp     = (const float*)d_in[15];
    const float* bkp     = (const float*)d_in[16];
    const float* Wvp     = (const float*)d_in[17];
    const float* bvp     = (const float*)d_in[18];
    const float* Wpb     = (const float*)d_in[19];
    const float* bpb     = (const float*)d_in[20];
    const float* Wo      = (const float*)d_in[21];
    const float* bo      = (const float*)d_in[22];
    const float* w_c     = (const float*)d_in[23];
    const float* w_l     = (const float*)d_in[24];
    const float* gamma_h = (const float*)d_in[25];

    k_ln<<<L, 384>>>(single_, ln_w, ln_b);
    k_projgemm<<<dim3(PROJD/64, L/64), 256>>>(Wq, bq, Wk, bk, Wv, bv,
                                              Wqp, bqp, Wkp, bkp, Wvp, bvp);
    k_rot<<<L, 384>>>(rot, trans, w_c, w_l, gamma_h);
    k_logits<<<dim3(L/64, L/64, H_), 256>>>();

    const int dyn = (2048 + 6192 + 9216 + 8448 + 512) * (int)sizeof(float);  // 105664
    cudaFuncSetAttribute(k_fused, cudaFuncAttributeMaxDynamicSharedMemorySize, dyn);
    k_fused<<<L, 256, dyn>>>(pair, Wpb, bpb, mask);

    k_av<<<dim3(H_, L/64), 256>>>();
    k_pts<<<(L*96 + 255)/256, 256>>>(rot, trans);
    k_final4<<<dim3(DS/64, L/64, 4), 256>>>(Wo);
    k_fred<<<192, 256>>>(bo, (float*)d_out);
}